// round 4
// baseline (speedup 1.0000x reference)
#include <cuda_runtime.h>
#include <cuda_bf16.h>
#include <math.h>

// ---------------- problem constants ----------------
#define BB   128
#define TT   1024
#define TCC  1024
#define LL   4
#define EE   256
#define HH   512
#define VTT  50000
#define OOVN 50
#define NOUT (VTT + OOVN)   // 50050
#define G4H  2048           // 4*H
#define KCAT 768            // E + H
#define DCAT 1024           // 2*H (d1,d2)

// ---------------- scratch (one big device buffer) ----------------
// offsets in floats
#define OFF_XCAT   0                        // 128*768
#define OFF_WCAT   (OFF_XCAT + BB*KCAT)     // 2048*768
#define OFF_WD     (OFF_WCAT + G4H*KCAT)    // 1024*512
#define OFF_GATES  (OFF_WD   + DCAT*HH)     // 128*2048
#define OFF_H      (OFF_GATES+ BB*G4H)      // 128*512
#define OFF_C      (OFF_H    + BB*HH)       // 128*512
#define OFF_D12    (OFF_C    + BB*HH)       // 128*1024
#define OFF_PCTX   (OFF_D12  + BB*DCAT)     // 2*128*8*512
#define OFF_PSUM   (OFF_PCTX + 2*BB*8*HH)   // 2*128*8
#define OFF_CTX    (OFF_PSUM + 2*BB*8)      // 2*128*512
#define OFF_CEXP   (OFF_CTX  + 2*BB*HH)     // 128*1024
#define OFF_CSUM   (OFF_CEXP + BB*TCC)      // 128
#define OFF_PGEN   (OFF_CSUM + BB)          // 128
#define OFF_CPS    (OFF_PGEN + BB)          // 128
#define OFF_RSUM   (OFF_CPS  + BB)          // 128
#define SCRATCH_FLOATS (OFF_RSUM + BB)

__device__ float g_scratch[SCRATCH_FLOATS];

// ---------------- helpers ----------------
__device__ __forceinline__ float sigf(float x) { return 1.0f / (1.0f + expf(-x)); }

// ---------------- prep: concat weights, bias-init accumulators, zero rowsum ----
__global__ void prep_kernel(const float* __restrict__ W_ih, const float* __restrict__ W_hh,
                            const float* __restrict__ attn_W, const float* __restrict__ cattn_W,
                            const float* __restrict__ b_ih, const float* __restrict__ b_hh,
                            const float* __restrict__ attn_b, const float* __restrict__ cattn_b,
                            float* __restrict__ scratch)
{
    const int WCATN = G4H * KCAT;        // 1572864
    const int WDN   = DCAT * HH;         // 524288
    const int GN    = BB * G4H;          // 262144
    const int DN    = BB * DCAT;         // 131072
    long idx = (long)blockIdx.x * blockDim.x + threadIdx.x;
    if (idx < WCATN) {
        int n = (int)(idx / KCAT), k = (int)(idx % KCAT);
        scratch[OFF_WCAT + idx] = (k < EE) ? W_ih[n*EE + k] : W_hh[n*HH + (k - EE)];
        return;
    }
    idx -= WCATN;
    if (idx < WDN) {
        int n = (int)(idx / HH), k = (int)(idx % HH);
        scratch[OFF_WD + idx] = (n < HH) ? attn_W[n*HH + k] : cattn_W[(n - HH)*HH + k];
        return;
    }
    idx -= WDN;
    if (idx < GN) {
        int n = (int)(idx % G4H);
        scratch[OFF_GATES + idx] = b_ih[n] + b_hh[n];
        return;
    }
    idx -= GN;
    if (idx < DN) {
        int n = (int)(idx % DCAT);
        scratch[OFF_D12 + idx] = (n < HH) ? attn_b[n] : cattn_b[n - HH];
        return;
    }
    idx -= DN;
    if (idx < BB) scratch[OFF_RSUM + idx] = 0.0f;
}

// ---------------- embed: x = tanh(mean of 4 emb rows); Xcat = [x, h0] ----------
__global__ void embed_kernel(const int* __restrict__ ids, const float* __restrict__ emb,
                             const float* __restrict__ h0, float* __restrict__ xcat)
{
    int b = blockIdx.x, tid = threadIdx.x;
    int i0 = ids[b*LL + 0], i1 = ids[b*LL + 1], i2 = ids[b*LL + 2], i3 = ids[b*LL + 3];
    if (tid < EE) {
        float s = emb[(long)i0*EE + tid] + emb[(long)i1*EE + tid]
                + emb[(long)i2*EE + tid] + emb[(long)i3*EE + tid];
        xcat[b*KCAT + tid] = tanhf(s * (1.0f / LL));
    }
    for (int j = tid; j < HH; j += blockDim.x)
        xcat[b*KCAT + EE + j] = h0[b*HH + j];
}

// ---------------- GEMM: C[128][N] (+)= X[128][K] @ W[N][K]^T -------------------
// 128x128 tile, 256 threads, 8x8 microtile as 4 f32x2 M-pairs x 8 N.
// mode 0: atomicAdd into C (C pre-initialized with bias), split-K via gridDim.y
// mode 1: C = exp(acc + bias); accumulate per-row sum into rowsum (KS must be 1)
__global__ __launch_bounds__(256)
void gemm_kernel(const float* __restrict__ X, int ldx,
                 const float* __restrict__ W, int ldw,
                 const float* __restrict__ bias,
                 float* __restrict__ C, int ldc,
                 int N, int K, int mode, float* __restrict__ rowsum)
{
    __shared__ float Xs[16][130];   // 130: keeps rows 8B-aligned, even pad
    __shared__ float Ws[16][132];   // 132: rows 16B-aligned for float4 reads
    __shared__ float rs_s[128];

    int n0   = blockIdx.x * 128;
    int klen = K / gridDim.y;       // divisible by 16 by construction
    int kbeg = blockIdx.y * klen;
    int tid  = threadIdx.x;
    int tm   = tid >> 4;            // 0..15 -> M rows tm*8..tm*8+7
    int tn   = tid & 15;            // 0..15 -> N cols tn*8..tn*8+7

    unsigned long long acc[4][8];
    #pragma unroll
    for (int p = 0; p < 4; p++)
        #pragma unroll
        for (int j = 0; j < 8; j++) acc[p][j] = 0ull;

    for (int k0 = kbeg; k0 < kbeg + klen; k0 += 16) {
        #pragma unroll
        for (int i = tid; i < 128*16; i += 256) {
            int m = i >> 4, k = i & 15;
            Xs[k][m] = X[(long)m*ldx + k0 + k];
        }
        #pragma unroll
        for (int i = tid; i < 128*16; i += 256) {
            int n = i >> 4, k = i & 15;
            int gn = n0 + n;
            Ws[k][n] = (gn < N) ? W[(long)gn*ldw + k0 + k] : 0.0f;
        }
        __syncthreads();
        #pragma unroll
        for (int k = 0; k < 16; k++) {
            unsigned long long rm[4];
            #pragma unroll
            for (int p = 0; p < 4; p++)
                rm[p] = *(const unsigned long long*)&Xs[k][tm*8 + 2*p];
            float4 w0 = *(const float4*)&Ws[k][tn*8];
            float4 w1 = *(const float4*)&Ws[k][tn*8 + 4];
            float wv[8] = {w0.x, w0.y, w0.z, w0.w, w1.x, w1.y, w1.z, w1.w};
            #pragma unroll
            for (int j = 0; j < 8; j++) {
                unsigned long long bv;
                asm("mov.b64 %0, {%1,%1};" : "=l"(bv) : "f"(wv[j]));
                #pragma unroll
                for (int p = 0; p < 4; p++)
                    asm("fma.rn.f32x2 %0, %1, %2, %0;"
                        : "+l"(acc[p][j]) : "l"(rm[p]), "l"(bv));
            }
        }
        __syncthreads();
    }

    if (mode == 0) {
        #pragma unroll
        for (int p = 0; p < 4; p++) {
            int m0 = tm*8 + 2*p;
            #pragma unroll
            for (int j = 0; j < 8; j++) {
                int n = n0 + tn*8 + j;
                if (n < N) {
                    float2 v = *(float2*)&acc[p][j];
                    atomicAdd(&C[(long)m0*ldc + n], v.x);
                    atomicAdd(&C[(long)(m0+1)*ldc + n], v.y);
                }
            }
        }
    } else {
        if (tid < 128) rs_s[tid] = 0.0f;
        __syncthreads();
        float rloc[8];
        #pragma unroll
        for (int r = 0; r < 8; r++) rloc[r] = 0.0f;
        #pragma unroll
        for (int p = 0; p < 4; p++) {
            int m0 = tm*8 + 2*p;
            #pragma unroll
            for (int j = 0; j < 8; j++) {
                int n = n0 + tn*8 + j;
                if (n < N) {
                    float2 v = *(float2*)&acc[p][j];
                    float e0 = expf(v.x + bias[n]);
                    float e1 = expf(v.y + bias[n]);
                    C[(long)m0*ldc + n]     = e0;
                    C[(long)(m0+1)*ldc + n] = e1;
                    rloc[2*p]   += e0;
                    rloc[2*p+1] += e1;
                }
            }
        }
        #pragma unroll
        for (int r = 0; r < 8; r++) atomicAdd(&rs_s[tm*8 + r], rloc[r]);
        __syncthreads();
        if (tid < 128) atomicAdd(&rowsum[tid], rs_s[tid]);
    }
}

// ---------------- LSTM pointwise ----------------
__global__ void lstm_kernel(const float* __restrict__ gates, const float* __restrict__ c0,
                            float* __restrict__ h, float* __restrict__ c,
                            float* __restrict__ dout, int write_hc)
{
    int b = blockIdx.x, j = threadIdx.x;
    float gi = gates[b*G4H + j];
    float gf = gates[b*G4H + HH + j];
    float gg = gates[b*G4H + 2*HH + j];
    float go = gates[b*G4H + 3*HH + j];
    float cp = c0[b*HH + j];
    float cn = sigf(gf) * cp + sigf(gi) * tanhf(gg);
    float hn = sigf(go) * tanhf(cn);
    h[b*HH + j] = hn;
    c[b*HH + j] = cn;
    if (write_hc) {
        dout[(long)BB*NOUT + b*HH + j]           = hn;
        dout[(long)BB*NOUT + BB*HH + b*HH + j]   = cn;
    }
}

// ---------------- one-pass attention (per B x T-chunk partials) ----------------
// Block: (b, chunk of 128 t). 8 warps, 16 t per warp. Computes partial
// sum_t exp(s_t)*e_t and sum_t exp(s_t). Optionally stores exp(s_t).
__global__ __launch_bounds__(256)
void attn_kernel(const float* __restrict__ enc, const float* __restrict__ dmat, int doff,
                 float* __restrict__ pctx, float* __restrict__ psum, float* __restrict__ cexp)
{
    int b = blockIdx.x, ch = blockIdx.y;
    int tid = threadIdx.x, lane = tid & 31, wid = tid >> 5;
    __shared__ float d_s[HH];
    __shared__ float acc_s[HH];
    __shared__ float sum_s[8];
    for (int i = tid; i < HH; i += 256) {
        d_s[i] = dmat[b*DCAT + doff + i];
        acc_s[i] = 0.0f;
    }
    __syncthreads();

    float acc[16];
    #pragma unroll
    for (int i = 0; i < 16; i++) acc[i] = 0.0f;
    float sume = 0.0f;

    int tbase = ch*128 + wid*16;
    const float* eb = enc + ((long)b*TT + tbase) * HH;
    for (int tt = 0; tt < 16; tt++) {
        const float* e = eb + (long)tt*HH;
        float4 ev[4];
        float s = 0.0f;
        #pragma unroll
        for (int i = 0; i < 4; i++) {
            int d0 = lane*4 + 128*i;
            ev[i] = *(const float4*)&e[d0];
            float4 dv = *(const float4*)&d_s[d0];
            s += ev[i].x*dv.x + ev[i].y*dv.y + ev[i].z*dv.z + ev[i].w*dv.w;
        }
        #pragma unroll
        for (int o = 16; o; o >>= 1) s += __shfl_xor_sync(0xFFFFFFFFu, s, o);
        float w = expf(s);
        sume += w;
        if (cexp != nullptr && lane == 0) cexp[b*TCC + tbase + tt] = w;
        #pragma unroll
        for (int i = 0; i < 4; i++) {
            acc[4*i+0] += w * ev[i].x;
            acc[4*i+1] += w * ev[i].y;
            acc[4*i+2] += w * ev[i].z;
            acc[4*i+3] += w * ev[i].w;
        }
    }
    #pragma unroll
    for (int i = 0; i < 16; i++) {
        int d = lane*4 + 128*(i >> 2) + (i & 3);
        atomicAdd(&acc_s[d], acc[i]);
    }
    if (lane == 0) sum_s[wid] = sume;
    __syncthreads();
    for (int i = tid; i < HH; i += 256)
        pctx[(long)(b*8 + ch)*HH + i] = acc_s[i];
    if (tid == 0) {
        float s = 0.0f;
        #pragma unroll
        for (int w = 0; w < 8; w++) s += sum_s[w];
        psum[b*8 + ch] = s;
    }
}

// ---------------- combine attention partials -> context vectors ----------------
__global__ void combine_kernel(const float* __restrict__ pctx, const float* __restrict__ psum,
                               float* __restrict__ ctx, float* __restrict__ csum)
{
    int b = blockIdx.x, a = blockIdx.y, d = threadIdx.x;
    const float* ps = psum + a*BB*8 + b*8;
    float ssum = 0.0f;
    #pragma unroll
    for (int ch = 0; ch < 8; ch++) ssum += ps[ch];
    const float* pc = pctx + (long)a*BB*8*HH + (long)b*8*HH;
    float cv = 0.0f;
    #pragma unroll
    for (int ch = 0; ch < 8; ch++) cv += pc[ch*HH + d];
    ctx[(long)(a*BB + b)*HH + d] = cv / ssum;
    if (a == 1 && d == 0) csum[b] = ssum;
}

// ---------------- p_gen: sigmoid(feat . gen_W + gen_b + sig_b), ctx_len guard --
__global__ void pgen_kernel(const float* __restrict__ ctx, const float* __restrict__ h,
                            const float* __restrict__ xcat, const float* __restrict__ gen_W,
                            const float* __restrict__ gen_b, const float* __restrict__ sig_b,
                            const int* __restrict__ ci, const float* __restrict__ csum,
                            float* __restrict__ pgen, float* __restrict__ cps)
{
    __shared__ float sred[256];
    __shared__ int   cred[256];
    int b = blockIdx.x, tid = threadIdx.x;
    float part = 0.0f;
    for (int i = tid; i < 3*HH + EE; i += 256) {
        float f;
        if (i < HH)           f = ctx[(long)b*HH + i];                 // context
        else if (i < 2*HH)    f = ctx[(long)(BB + b)*HH + (i - HH)];   // context_context
        else if (i < 3*HH)    f = h[b*HH + (i - 2*HH)];                // dec
        else                  f = xcat[b*KCAT + (i - 3*HH)];           // x
        part += f * gen_W[i];
    }
    int cnt = 0;
    for (int t = tid; t < TCC; t += 256) cnt += (ci[b*TCC + t] > 0) ? 1 : 0;
    sred[tid] = part; cred[tid] = cnt;
    __syncthreads();
    for (int o = 128; o; o >>= 1) {
        if (tid < o) { sred[tid] += sred[tid + o]; cred[tid] += cred[tid + o]; }
        __syncthreads();
    }
    if (tid == 0) {
        float z = sred[0] + gen_b[0] + sig_b[0];
        float p = sigf(z);
        if (cred[0] == 0) p = 1.0f;
        pgen[b] = p;
        cps[b]  = (1.0f - p) / csum[b];
    }
}

// ---------------- normalize p_vocab: prob = p_gen * exp / rowsum; OOV cols = 0 -
__global__ void norm_kernel(float* __restrict__ dout, const float* __restrict__ pgen,
                            const float* __restrict__ rowsum)
{
    long idx = (long)blockIdx.x * blockDim.x + threadIdx.x;
    if (idx >= (long)BB*NOUT) return;
    int b = (int)(idx / NOUT);
    int v = (int)(idx % NOUT);
    if (v < VTT) dout[idx] = dout[idx] * pgen[b] / rowsum[b];
    else         dout[idx] = 0.0f;
}

// ---------------- scatter copy-mass: prob[b][ci[b][t]] += cps[b]*cexp[b][t] ----
__global__ void scatter_kernel(float* __restrict__ dout, const int* __restrict__ ci,
                               const float* __restrict__ cexp, const float* __restrict__ cps)
{
    int b = blockIdx.x;
    int t = blockIdx.y * 256 + threadIdx.x;
    int idx = ci[b*TCC + t];
    atomicAdd(&dout[(long)b*NOUT + idx], cps[b] * cexp[b*TCC + t]);
}

// ---------------- final log with clip ----------------
__global__ void log_kernel(float* __restrict__ dout)
{
    long idx = (long)blockIdx.x * blockDim.x + threadIdx.x;
    if (idx >= (long)BB*NOUT) return;
    dout[idx] = logf(fmaxf(dout[idx], 1e-10f));
}

// ---------------- launcher ----------------
extern "C" void kernel_launch(void* const* d_in, const int* in_sizes, int n_in,
                              void* d_out, int out_size)
{
    const int*   ids     = (const int*)  d_in[0];
    const float* h0      = (const float*)d_in[1];
    const float* c0      = (const float*)d_in[2];
    const float* enc     = (const float*)d_in[3];
    const float* cenc    = (const float*)d_in[4];
    const int*   ci      = (const int*)  d_in[5];
    const float* emb     = (const float*)d_in[6];
    const float* W_ih    = (const float*)d_in[7];
    const float* W_hh    = (const float*)d_in[8];
    const float* b_ih    = (const float*)d_in[9];
    const float* b_hh    = (const float*)d_in[10];
    const float* attn_W  = (const float*)d_in[11];
    const float* attn_b  = (const float*)d_in[12];
    const float* cattn_W = (const float*)d_in[13];
    const float* cattn_b = (const float*)d_in[14];
    const float* gen_W   = (const float*)d_in[15];
    const float* gen_b   = (const float*)d_in[16];
    const float* sig_b   = (const float*)d_in[17];
    const float* out_W   = (const float*)d_in[18];
    const float* out_b   = (const float*)d_in[19];
    float* dout = (float*)d_out;

    float* S = nullptr;
    cudaGetSymbolAddress((void**)&S, g_scratch);
    float* xcat  = S + OFF_XCAT;
    float* wcat  = S + OFF_WCAT;
    float* wd    = S + OFF_WD;
    float* gates = S + OFF_GATES;
    float* hbuf  = S + OFF_H;
    float* cbuf  = S + OFF_C;
    float* d12   = S + OFF_D12;
    float* pctx  = S + OFF_PCTX;
    float* psum  = S + OFF_PSUM;
    float* ctx   = S + OFF_CTX;
    float* cexp  = S + OFF_CEXP;
    float* csum  = S + OFF_CSUM;
    float* pgen  = S + OFF_PGEN;
    float* cps   = S + OFF_CPS;
    float* rsum  = S + OFF_RSUM;

    const long prep_n = (long)G4H*KCAT + (long)DCAT*HH + (long)BB*G4H + (long)BB*DCAT + BB;
    prep_kernel<<<(int)((prep_n + 255) / 256), 256>>>(W_ih, W_hh, attn_W, cattn_W,
                                                      b_ih, b_hh, attn_b, cattn_b, S);

    embed_kernel<<<BB, 256>>>(ids, emb, h0, xcat);

    // gates = Xcat @ Wcat^T (+bias preinit), split-K=8 -> 128 blocks
    gemm_kernel<<<dim3(G4H/128, 8), 256>>>(xcat, KCAT, wcat, KCAT, nullptr,
                                           gates, G4H, G4H, KCAT, 0, nullptr);

    int write_hc = (out_size >= BB*NOUT + 2*BB*HH) ? 1 : 0;
    lstm_kernel<<<BB, HH>>>(gates, c0, hbuf, cbuf, dout, write_hc);

    // d12 = dec @ [attn_W;cattn_W]^T (+bias preinit), split-K=8 -> 64 blocks
    gemm_kernel<<<dim3(DCAT/128, 8), 256>>>(hbuf, HH, wd, HH, nullptr,
                                            d12, DCAT, DCAT, HH, 0, nullptr);

    // source attention (a=0) and context attention (a=1, stores exp scores)
    attn_kernel<<<dim3(BB, 8), 256>>>(enc,  d12, 0,   pctx,             psum,        nullptr);
    attn_kernel<<<dim3(BB, 8), 256>>>(cenc, d12, HH,  pctx + BB*8*HH,   psum + BB*8, cexp);

    combine_kernel<<<dim3(BB, 2), HH>>>(pctx, psum, ctx, csum);

    pgen_kernel<<<BB, 256>>>(ctx, hbuf, xcat, gen_W, gen_b, sig_b, ci, csum, pgen, cps);

    // out logits -> exp + rowsum, written straight into d_out at ldc=50050
    gemm_kernel<<<dim3((VTT + 127) / 128, 1), 256>>>(hbuf, HH, out_W, HH, out_b,
                                                     dout, NOUT, VTT, HH, 1, rsum);

    long nout_total = (long)BB * NOUT;
    norm_kernel<<<(int)((nout_total + 255) / 256), 256>>>(dout, pgen, rsum);
    scatter_kernel<<<dim3(BB, TCC/256), 256>>>(dout, ci, cexp, cps);
    log_kernel<<<(int)((nout_total + 255) / 256), 256>>>(dout);
}

// round 6
// speedup vs baseline: 1.6337x; 1.6337x over previous
#include <cuda_runtime.h>
#include <cuda_bf16.h>
#include <math.h>
#include <stdint.h>

// ---------------- problem constants ----------------
#define BB   128
#define TT   1024
#define TCC  1024
#define LL   4
#define EE   256
#define HH   512
#define VTT  50000
#define OOVN 50
#define NOUT (VTT + OOVN)   // 50050
#define G4H  2048           // 4*H
#define KCAT 768            // E + H
#define DCAT 1024           // 2*H (d1,d2)
#define OGTILES ((VTT + 63) / 64)    // 782

// ---------------- scratch ----------------
#define OFF_XCAT   0                        // 128*768
#define OFF_WCAT   (OFF_XCAT + BB*KCAT)     // 2048*768
#define OFF_WD     (OFF_WCAT + G4H*KCAT)    // 1024*512
#define OFF_GATES  (OFF_WD   + DCAT*HH)     // 128*2048
#define OFF_H      (OFF_GATES+ BB*G4H)      // 128*512
#define OFF_C      (OFF_H    + BB*HH)       // 128*512
#define OFF_D12    (OFF_C    + BB*HH)       // 128*1024
#define OFF_PCTX   (OFF_D12  + BB*DCAT)     // 2*128*8*512
#define OFF_PSUM   (OFF_PCTX + 2*BB*8*HH)   // 2*128*8
#define OFF_CTX    (OFF_PSUM + 2*BB*8)      // 2*128*512
#define OFF_CEXP   (OFF_CTX  + 2*BB*HH)     // 128*1024
#define OFF_CSUM   (OFF_CEXP + BB*TCC)      // 128
#define OFF_PGEN   (OFF_CSUM + BB)          // 128
#define OFF_CPS    (OFF_PGEN + BB)          // 128
#define OFF_RSUM   (OFF_CPS  + BB)          // 128
#define SCRATCH_FLOATS (OFF_RSUM + BB)

__device__ float g_scratch[SCRATCH_FLOATS];
__device__ __nv_bfloat16 g_hbf[BB * HH];    // h in bf16 (row-major [b][k])

// ---------------- helpers ----------------
__device__ __forceinline__ float sigf(float x) { return 1.0f / (1.0f + expf(-x)); }

__device__ __forceinline__ uint32_t smem_u32(const void* p) {
    uint32_t a;
    asm("{ .reg .u64 t; cvta.to.shared.u64 t, %1; cvt.u32.u64 %0, t; }" : "=r"(a) : "l"(p));
    return a;
}

// ---------------- prep ----------------
__global__ void prep_kernel(const float* __restrict__ W_ih, const float* __restrict__ W_hh,
                            const float* __restrict__ attn_W, const float* __restrict__ cattn_W,
                            const float* __restrict__ b_ih, const float* __restrict__ b_hh,
                            const float* __restrict__ attn_b, const float* __restrict__ cattn_b,
                            float* __restrict__ scratch)
{
    const int WCATN = G4H * KCAT;
    const int WDN   = DCAT * HH;
    const int GN    = BB * G4H;
    const int DN    = BB * DCAT;
    long idx = (long)blockIdx.x * blockDim.x + threadIdx.x;
    if (idx < WCATN) {
        int n = (int)(idx / KCAT), k = (int)(idx % KCAT);
        scratch[OFF_WCAT + idx] = (k < EE) ? W_ih[n*EE + k] : W_hh[n*HH + (k - EE)];
        return;
    }
    idx -= WCATN;
    if (idx < WDN) {
        int n = (int)(idx / HH), k = (int)(idx % HH);
        scratch[OFF_WD + idx] = (n < HH) ? attn_W[n*HH + k] : cattn_W[(n - HH)*HH + k];
        return;
    }
    idx -= WDN;
    if (idx < GN) {
        int n = (int)(idx % G4H);
        scratch[OFF_GATES + idx] = b_ih[n] + b_hh[n];
        return;
    }
    idx -= GN;
    if (idx < DN) {
        int n = (int)(idx % DCAT);
        scratch[OFF_D12 + idx] = (n < HH) ? attn_b[n] : cattn_b[n - HH];
        return;
    }
    idx -= DN;
    if (idx < BB) scratch[OFF_RSUM + idx] = 0.0f;
}

// ---------------- embed ----------------
__global__ void embed_kernel(const int* __restrict__ ids, const float* __restrict__ emb,
                             const float* __restrict__ h0, float* __restrict__ xcat)
{
    int b = blockIdx.x, tid = threadIdx.x;
    int i0 = ids[b*LL + 0], i1 = ids[b*LL + 1], i2 = ids[b*LL + 2], i3 = ids[b*LL + 3];
    if (tid < EE) {
        float s = emb[(long)i0*EE + tid] + emb[(long)i1*EE + tid]
                + emb[(long)i2*EE + tid] + emb[(long)i3*EE + tid];
        xcat[b*KCAT + tid] = tanhf(s * (1.0f / LL));
    }
    for (int j = tid; j < HH; j += blockDim.x)
        xcat[b*KCAT + EE + j] = h0[b*HH + j];
}

// ---------------- small-GEMM (fp32 f32x2) -- gates and d12 -------------------
__global__ __launch_bounds__(256)
void gemm_kernel(const float* __restrict__ X, int ldx,
                 const float* __restrict__ W, int ldw,
                 float* __restrict__ C, int ldc, int N, int K)
{
    __shared__ float Xs[16][130];
    __shared__ float Ws[16][132];

    int n0   = blockIdx.x * 128;
    int klen = K / gridDim.y;
    int kbeg = blockIdx.y * klen;
    int tid  = threadIdx.x;
    int tm   = tid >> 4;
    int tn   = tid & 15;

    unsigned long long acc[4][8];
    #pragma unroll
    for (int p = 0; p < 4; p++)
        #pragma unroll
        for (int j = 0; j < 8; j++) acc[p][j] = 0ull;

    for (int k0 = kbeg; k0 < kbeg + klen; k0 += 16) {
        #pragma unroll
        for (int i = tid; i < 128*16; i += 256) {
            int m = i >> 4, k = i & 15;
            Xs[k][m] = X[(long)m*ldx + k0 + k];
        }
        #pragma unroll
        for (int i = tid; i < 128*16; i += 256) {
            int n = i >> 4, k = i & 15;
            int gn = n0 + n;
            Ws[k][n] = (gn < N) ? W[(long)gn*ldw + k0 + k] : 0.0f;
        }
        __syncthreads();
        #pragma unroll
        for (int k = 0; k < 16; k++) {
            unsigned long long rm[4];
            #pragma unroll
            for (int p = 0; p < 4; p++)
                rm[p] = *(const unsigned long long*)&Xs[k][tm*8 + 2*p];
            float4 w0 = *(const float4*)&Ws[k][tn*8];
            float4 w1 = *(const float4*)&Ws[k][tn*8 + 4];
            float wv[8] = {w0.x, w0.y, w0.z, w0.w, w1.x, w1.y, w1.z, w1.w};
            #pragma unroll
            for (int j = 0; j < 8; j++) {
                unsigned long long bv;
                asm("mov.b64 %0, {%1,%1};" : "=l"(bv) : "f"(wv[j]));
                #pragma unroll
                for (int p = 0; p < 4; p++)
                    asm("fma.rn.f32x2 %0, %1, %2, %0;"
                        : "+l"(acc[p][j]) : "l"(rm[p]), "l"(bv));
            }
        }
        __syncthreads();
    }

    #pragma unroll
    for (int p = 0; p < 4; p++) {
        int m0 = tm*8 + 2*p;
        #pragma unroll
        for (int j = 0; j < 8; j++) {
            int n = n0 + tn*8 + j;
            if (n < N) {
                float2 v = *(float2*)&acc[p][j];
                atomicAdd(&C[(long)m0*ldc + n], v.x);
                atomicAdd(&C[(long)(m0+1)*ldc + n], v.y);
            }
        }
    }
}

// ---------------- LSTM pointwise (+ bf16 h for tensor GEMM) ----------------
__global__ void lstm_kernel(const float* __restrict__ gates, const float* __restrict__ c0,
                            float* __restrict__ h, float* __restrict__ c,
                            __nv_bfloat16* __restrict__ hbf,
                            float* __restrict__ dout, int write_hc)
{
    int b = blockIdx.x, j = threadIdx.x;
    float gi = gates[b*G4H + j];
    float gf = gates[b*G4H + HH + j];
    float gg = gates[b*G4H + 2*HH + j];
    float go = gates[b*G4H + 3*HH + j];
    float cp = c0[b*HH + j];
    float cn = sigf(gf) * cp + sigf(gi) * tanhf(gg);
    float hn = sigf(go) * tanhf(cn);
    h[b*HH + j] = hn;
    c[b*HH + j] = cn;
    hbf[b*HH + j] = __float2bfloat16(hn);
    if (write_hc) {
        dout[(long)BB*NOUT + b*HH + j]           = hn;
        dout[(long)BB*NOUT + BB*HH + b*HH + j]   = cn;
    }
}

// ---------------- one-pass attention ----------------
__global__ __launch_bounds__(256)
void attn_kernel(const float* __restrict__ enc, const float* __restrict__ dmat, int doff,
                 float* __restrict__ pctx, float* __restrict__ psum, float* __restrict__ cexp)
{
    int b = blockIdx.x, ch = blockIdx.y;
    int tid = threadIdx.x, lane = tid & 31, wid = tid >> 5;
    __shared__ float d_s[HH];
    __shared__ float acc_s[HH];
    __shared__ float sum_s[8];
    for (int i = tid; i < HH; i += 256) {
        d_s[i] = dmat[b*DCAT + doff + i];
        acc_s[i] = 0.0f;
    }
    __syncthreads();

    float acc[16];
    #pragma unroll
    for (int i = 0; i < 16; i++) acc[i] = 0.0f;
    float sume = 0.0f;

    int tbase = ch*128 + wid*16;
    const float* eb = enc + ((long)b*TT + tbase) * HH;
    for (int tt = 0; tt < 16; tt++) {
        const float* e = eb + (long)tt*HH;
        float4 ev[4];
        float s = 0.0f;
        #pragma unroll
        for (int i = 0; i < 4; i++) {
            int d0 = lane*4 + 128*i;
            ev[i] = *(const float4*)&e[d0];
            float4 dv = *(const float4*)&d_s[d0];
            s += ev[i].x*dv.x + ev[i].y*dv.y + ev[i].z*dv.z + ev[i].w*dv.w;
        }
        #pragma unroll
        for (int o = 16; o; o >>= 1) s += __shfl_xor_sync(0xFFFFFFFFu, s, o);
        float w = expf(s);
        sume += w;
        if (cexp != nullptr && lane == 0) cexp[b*TCC + tbase + tt] = w;
        #pragma unroll
        for (int i = 0; i < 4; i++) {
            acc[4*i+0] += w * ev[i].x;
            acc[4*i+1] += w * ev[i].y;
            acc[4*i+2] += w * ev[i].z;
            acc[4*i+3] += w * ev[i].w;
        }
    }
    #pragma unroll
    for (int i = 0; i < 16; i++) {
        int d = lane*4 + 128*(i >> 2) + (i & 3);
        atomicAdd(&acc_s[d], acc[i]);
    }
    if (lane == 0) sum_s[wid] = sume;
    __syncthreads();
    for (int i = tid; i < HH; i += 256)
        pctx[(long)(b*8 + ch)*HH + i] = acc_s[i];
    if (tid == 0) {
        float s = 0.0f;
        #pragma unroll
        for (int w = 0; w < 8; w++) s += sum_s[w];
        psum[b*8 + ch] = s;
    }
}

// ---------------- combine attention partials ----------------
__global__ void combine_kernel(const float* __restrict__ pctx, const float* __restrict__ psum,
                               float* __restrict__ ctx, float* __restrict__ csum)
{
    int b = blockIdx.x, a = blockIdx.y, d = threadIdx.x;
    const float* ps = psum + a*BB*8 + b*8;
    float ssum = 0.0f;
    #pragma unroll
    for (int ch = 0; ch < 8; ch++) ssum += ps[ch];
    const float* pc = pctx + (long)a*BB*8*HH + (long)b*8*HH;
    float cv = 0.0f;
    #pragma unroll
    for (int ch = 0; ch < 8; ch++) cv += pc[ch*HH + d];
    ctx[(long)(a*BB + b)*HH + d] = cv / ssum;
    if (a == 1 && d == 0) csum[b] = ssum;
}

// ---------------- p_gen ----------------
__global__ void pgen_kernel(const float* __restrict__ ctx, const float* __restrict__ h,
                            const float* __restrict__ xcat, const float* __restrict__ gen_W,
                            const float* __restrict__ gen_b, const float* __restrict__ sig_b,
                            const int* __restrict__ ci, const float* __restrict__ csum,
                            float* __restrict__ pgen, float* __restrict__ cps)
{
    __shared__ float sred[256];
    __shared__ int   cred[256];
    int b = blockIdx.x, tid = threadIdx.x;
    float part = 0.0f;
    for (int i = tid; i < 3*HH + EE; i += 256) {
        float f;
        if (i < HH)           f = ctx[(long)b*HH + i];
        else if (i < 2*HH)    f = ctx[(long)(BB + b)*HH + (i - HH)];
        else if (i < 3*HH)    f = h[b*HH + (i - 2*HH)];
        else                  f = xcat[b*KCAT + (i - 3*HH)];
        part += f * gen_W[i];
    }
    int cnt = 0;
    for (int t = tid; t < TCC; t += 256) cnt += (ci[b*TCC + t] > 0) ? 1 : 0;
    sred[tid] = part; cred[tid] = cnt;
    __syncthreads();
    for (int o = 128; o; o >>= 1) {
        if (tid < o) { sred[tid] += sred[tid + o]; cred[tid] += cred[tid + o]; }
        __syncthreads();
    }
    if (tid == 0) {
        float z = sred[0] + gen_b[0] + sig_b[0];
        float p = sigf(z);
        if (cred[0] == 0) p = 1.0f;
        pgen[b] = p;
        cps[b]  = (1.0f - p) / csum[b];
    }
}

// ---------------- HMMA bf16 out-projection (base-target mma.sync) -----------
// CTA: 128 threads (4 warps), tile M=128 x N=64, K=512 in 8 chunks of 64.
// Warp w owns N-slab [w*16, w*16+16): 2 n8 frags x 8 m16 frags.
// A = h bf16 [128x512] row-major; B = out_W fp32 -> bf16 [n][k] (mma col operand).
// Epilogue: exp(acc+bias) -> direct float2 stores (quad = 32B sector), rowsum.
#define OG_KCH 64
#define OG_SA  72   // bf16 row stride (conflict-free ldmatrix phases)
#define OG_SB  72

__global__ __launch_bounds__(128, 4)
void outgemm_kernel(const __nv_bfloat16* __restrict__ hbf,
                    const float* __restrict__ W,
                    const float* __restrict__ bias,
                    float* __restrict__ dout,
                    float* __restrict__ rowsum)
{
    __shared__ __nv_bfloat16 As[128 * OG_SA];   // 18432 B
    __shared__ __nv_bfloat16 Bs[64  * OG_SB];   // 9216 B
    __shared__ float bias_s[64];
    __shared__ float rs_s[128];

    int tid = threadIdx.x, lane = tid & 31, warp = tid >> 5;
    int n0 = blockIdx.x * 64;

    if (tid < 64) { int n = n0 + tid; bias_s[tid] = (n < VTT) ? bias[n] : 0.0f; }
    rs_s[tid] = 0.0f;

    uint32_t as_b = smem_u32(As);
    uint32_t bs_b = smem_u32(Bs);

    float acc[8][2][4];
    #pragma unroll
    for (int mf = 0; mf < 8; mf++)
        #pragma unroll
        for (int nf = 0; nf < 2; nf++)
            #pragma unroll
            for (int r = 0; r < 4; r++) acc[mf][nf][r] = 0.0f;

    for (int kc = 0; kc < HH; kc += OG_KCH) {
        // A chunk: 128 x 64 bf16 (1024 uint4), 8 per thread
        #pragma unroll
        for (int it = 0; it < 8; it++) {
            int idx = it*128 + tid;
            int m = idx >> 3, kg = idx & 7;
            uint4 v = *(const uint4*)(hbf + (size_t)m*HH + kc + kg*8);
            *(uint4*)(As + m*OG_SA + kg*8) = v;
        }
        // B chunk: 64 x 64, fp32 -> bf16 (512 uint4), 4 per thread
        #pragma unroll
        for (int it = 0; it < 4; it++) {
            int idx = it*128 + tid;
            int r = idx >> 3, kg = idx & 7;
            int gn = n0 + r;
            float4 v0, v1;
            if (gn < VTT) {
                const float* wp = W + (size_t)gn*HH + kc + kg*8;
                v0 = *(const float4*)wp;
                v1 = *(const float4*)(wp + 4);
            } else {
                v0 = make_float4(0.f,0.f,0.f,0.f);
                v1 = v0;
            }
            __nv_bfloat162 p0 = __floats2bfloat162_rn(v0.x, v0.y);
            __nv_bfloat162 p1 = __floats2bfloat162_rn(v0.z, v0.w);
            __nv_bfloat162 p2 = __floats2bfloat162_rn(v1.x, v1.y);
            __nv_bfloat162 p3 = __floats2bfloat162_rn(v1.z, v1.w);
            uint4 pk;
            pk.x = *reinterpret_cast<uint32_t*>(&p0);
            pk.y = *reinterpret_cast<uint32_t*>(&p1);
            pk.z = *reinterpret_cast<uint32_t*>(&p2);
            pk.w = *reinterpret_cast<uint32_t*>(&p3);
            *(uint4*)(Bs + r*OG_SB + kg*8) = pk;
        }
        __syncthreads();

        #pragma unroll
        for (int ks = 0; ks < 4; ks++) {
            int k0 = ks * 16;
            uint32_t a[8][4];
            #pragma unroll
            for (int mf = 0; mf < 8; mf++) {
                uint32_t addr = as_b + (uint32_t)(((mf*16 + (lane & 15))*OG_SA + k0 + (lane >> 4)*8) * 2);
                asm volatile("ldmatrix.sync.aligned.m8n8.x4.shared.b16 {%0,%1,%2,%3}, [%4];"
                    : "=r"(a[mf][0]), "=r"(a[mf][1]), "=r"(a[mf][2]), "=r"(a[mf][3]) : "r"(addr));
            }
            #pragma unroll
            for (int nf = 0; nf < 2; nf++) {
                uint32_t b0, b1;
                uint32_t baddr = bs_b + (uint32_t)(((warp*16 + nf*8 + (lane & 7))*OG_SB
                                                    + k0 + ((lane >> 3) & 1)*8) * 2);
                asm volatile("ldmatrix.sync.aligned.m8n8.x2.shared.b16 {%0,%1}, [%2];"
                    : "=r"(b0), "=r"(b1) : "r"(baddr));
                #pragma unroll
                for (int mf = 0; mf < 8; mf++) {
                    asm volatile("mma.sync.aligned.m16n8k16.row.col.f32.bf16.bf16.f32 "
                        "{%0,%1,%2,%3}, {%4,%5,%6,%7}, {%8,%9}, {%0,%1,%2,%3};"
                        : "+f"(acc[mf][nf][0]), "+f"(acc[mf][nf][1]),
                          "+f"(acc[mf][nf][2]), "+f"(acc[mf][nf][3])
                        : "r"(a[mf][0]), "r"(a[mf][1]), "r"(a[mf][2]), "r"(a[mf][3]),
                          "r"(b0), "r"(b1));
                }
            }
        }
        __syncthreads();
    }

    // epilogue: exp(+bias), coalesced float2 stores, rowsum
    float rsp1[8], rsp2[8];
    #pragma unroll
    for (int mf = 0; mf < 8; mf++) { rsp1[mf] = 0.0f; rsp2[mf] = 0.0f; }

    #pragma unroll
    for (int mf = 0; mf < 8; mf++) {
        int r1 = mf*16 + (lane >> 2);
        #pragma unroll
        for (int nf = 0; nf < 2; nf++) {
            int ln = warp*16 + nf*8 + (lane & 3)*2;
            int gn = n0 + ln;
            float bv0 = bias_s[ln], bv1 = bias_s[ln + 1];
            float e0 = expf(acc[mf][nf][0] + bv0);
            float e1 = expf(acc[mf][nf][1] + bv1);
            float e2 = expf(acc[mf][nf][2] + bv0);
            float e3 = expf(acc[mf][nf][3] + bv1);
            float2 w0 = make_float2(e0, e1);
            float2 w1 = make_float2(e2, e3);
            *(float2*)&dout[(long)r1*NOUT + gn]       = w0;
            *(float2*)&dout[(long)(r1 + 8)*NOUT + gn] = w1;
            if (gn < VTT) { rsp1[mf] += e0 + e1; rsp2[mf] += e2 + e3; }
        }
    }
    #pragma unroll
    for (int mf = 0; mf < 8; mf++) {
        float s1 = rsp1[mf], s2 = rsp2[mf];
        s1 += __shfl_xor_sync(0xFFFFFFFFu, s1, 1);
        s1 += __shfl_xor_sync(0xFFFFFFFFu, s1, 2);
        s2 += __shfl_xor_sync(0xFFFFFFFFu, s2, 1);
        s2 += __shfl_xor_sync(0xFFFFFFFFu, s2, 2);
        if ((lane & 3) == 0) {
            atomicAdd(&rs_s[mf*16 + (lane >> 2)], s1);
            atomicAdd(&rs_s[mf*16 + (lane >> 2) + 8], s2);
        }
    }
    __syncthreads();
    atomicAdd(&rowsum[tid], rs_s[tid]);
}

// ---------------- normalize p_vocab ----------------
__global__ void norm_kernel(float* __restrict__ dout, const float* __restrict__ pgen,
                            const float* __restrict__ rowsum)
{
    long idx = (long)blockIdx.x * blockDim.x + threadIdx.x;
    if (idx >= (long)BB*NOUT) return;
    int b = (int)(idx / NOUT);
    int v = (int)(idx % NOUT);
    if (v < VTT) dout[idx] = dout[idx] * pgen[b] / rowsum[b];
    else         dout[idx] = 0.0f;
}

// ---------------- scatter copy-mass ----------------
__global__ void scatter_kernel(float* __restrict__ dout, const int* __restrict__ ci,
                               const float* __restrict__ cexp, const float* __restrict__ cps)
{
    int b = blockIdx.x;
    int t = blockIdx.y * 256 + threadIdx.x;
    int idx = ci[b*TCC + t];
    atomicAdd(&dout[(long)b*NOUT + idx], cps[b] * cexp[b*TCC + t]);
}

// ---------------- final log ----------------
__global__ void log_kernel(float* __restrict__ dout)
{
    long idx = (long)blockIdx.x * blockDim.x + threadIdx.x;
    if (idx >= (long)BB*NOUT) return;
    dout[idx] = logf(fmaxf(dout[idx], 1e-10f));
}

// ---------------- launcher ----------------
extern "C" void kernel_launch(void* const* d_in, const int* in_sizes, int n_in,
                              void* d_out, int out_size)
{
    const int*   ids     = (const int*)  d_in[0];
    const float* h0      = (const float*)d_in[1];
    const float* c0      = (const float*)d_in[2];
    const float* enc     = (const float*)d_in[3];
    const float* cenc    = (const float*)d_in[4];
    const int*   ci      = (const int*)  d_in[5];
    const float* emb     = (const float*)d_in[6];
    const float* W_ih    = (const float*)d_in[7];
    const float* W_hh    = (const float*)d_in[8];
    const float* b_ih    = (const float*)d_in[9];
    const float* b_hh    = (const float*)d_in[10];
    const float* attn_W  = (const float*)d_in[11];
    const float* attn_b  = (const float*)d_in[12];
    const float* cattn_W = (const float*)d_in[13];
    const float* cattn_b = (const float*)d_in[14];
    const float* gen_W   = (const float*)d_in[15];
    const float* gen_b   = (const float*)d_in[16];
    const float* sig_b   = (const float*)d_in[17];
    const float* out_W   = (const float*)d_in[18];
    const float* out_b   = (const float*)d_in[19];
    float* dout = (float*)d_out;

    float* S = nullptr;
    cudaGetSymbolAddress((void**)&S, g_scratch);
    __nv_bfloat16* hbf = nullptr;
    cudaGetSymbolAddress((void**)&hbf, g_hbf);

    float* xcat  = S + OFF_XCAT;
    float* wcat  = S + OFF_WCAT;
    float* wd    = S + OFF_WD;
    float* gates = S + OFF_GATES;
    float* hbuf  = S + OFF_H;
    float* cbuf  = S + OFF_C;
    float* d12   = S + OFF_D12;
    float* pctx  = S + OFF_PCTX;
    float* psum  = S + OFF_PSUM;
    float* ctx   = S + OFF_CTX;
    float* cexp  = S + OFF_CEXP;
    float* csum  = S + OFF_CSUM;
    float* pgen  = S + OFF_PGEN;
    float* cps   = S + OFF_CPS;
    float* rsum  = S + OFF_RSUM;

    const long prep_n = (long)G4H*KCAT + (long)DCAT*HH + (long)BB*G4H + (long)BB*DCAT + BB;
    prep_kernel<<<(int)((prep_n + 255) / 256), 256>>>(W_ih, W_hh, attn_W, cattn_W,
                                                      b_ih, b_hh, attn_b, cattn_b, S);

    embed_kernel<<<BB, 256>>>(ids, emb, h0, xcat);

    // gates = Xcat @ Wcat^T (+bias preinit), split-K=8
    gemm_kernel<<<dim3(G4H/128, 8), 256>>>(xcat, KCAT, wcat, KCAT, gates, G4H, G4H, KCAT);

    int write_hc = (out_size >= BB*NOUT + 2*BB*HH) ? 1 : 0;
    lstm_kernel<<<BB, HH>>>(gates, c0, hbuf, cbuf, hbf, dout, write_hc);

    // d12 = dec @ [attn_W;cattn_W]^T (+bias preinit), split-K=8
    gemm_kernel<<<dim3(DCAT/128, 8), 256>>>(hbuf, HH, wd, HH, d12, DCAT, DCAT, HH);

    // out logits -> exp + rowsum via HMMA bf16 (independent of attention; launch early)
    outgemm_kernel<<<OGTILES, 128>>>(hbf, out_W, out_b, dout, rsum);

    // source attention (a=0) and context attention (a=1, stores exp scores)
    attn_kernel<<<dim3(BB, 8), 256>>>(enc,  d12, 0,   pctx,             psum,        nullptr);
    attn_kernel<<<dim3(BB, 8), 256>>>(cenc, d12, HH,  pctx + BB*8*HH,   psum + BB*8, cexp);

    combine_kernel<<<dim3(BB, 2), HH>>>(pctx, psum, ctx, csum);

    pgen_kernel<<<BB, 256>>>(ctx, hbuf, xcat, gen_W, gen_b, sig_b, ci, csum, pgen, cps);

    long nout_total = (long)BB * NOUT;
    norm_kernel<<<(int)((nout_total + 255) / 256), 256>>>(dout, pgen, rsum);
    scatter_kernel<<<dim3(BB, TCC/256), 256>>>(dout, ci, cexp, cps);
    log_kernel<<<(int)((nout_total + 255) / 256), 256>>>(dout);
}

// round 9
// speedup vs baseline: 1.8249x; 1.1171x over previous
#include <cuda_runtime.h>
#include <cuda_bf16.h>
#include <math.h>
#include <stdint.h>

// ---------------- problem constants ----------------
#define BB   128
#define TT   1024
#define TCC  1024
#define LL   4
#define EE   256
#define HH   512
#define VTT  50000
#define OOVN 50
#define NOUT (VTT + OOVN)   // 50050
#define G4H  2048           // 4*H
#define KCAT 768            // E + H
#define DCAT 1024           // 2*H (d1,d2)
#define OGTILES ((VTT + 63) / 64)    // 782

// ---------------- scratch ----------------
#define OFF_XCAT   0                        // 128*768
#define OFF_WCAT   (OFF_XCAT + BB*KCAT)     // 2048*768
#define OFF_WD     (OFF_WCAT + G4H*KCAT)    // 1024*512
#define OFF_GATES  (OFF_WD   + DCAT*HH)     // 128*2048
#define OFF_H      (OFF_GATES+ BB*G4H)      // 128*512
#define OFF_C      (OFF_H    + BB*HH)       // 128*512
#define OFF_D12    (OFF_C    + BB*HH)       // 128*1024
#define OFF_PCTX   (OFF_D12  + BB*DCAT)     // 2*128*8*512
#define OFF_PSUM   (OFF_PCTX + 2*BB*8*HH)   // 2*128*8
#define OFF_CTX    (OFF_PSUM + 2*BB*8)      // 2*128*512
#define OFF_CEXP   (OFF_CTX  + 2*BB*HH)     // 128*1024
#define OFF_CSUM   (OFF_CEXP + BB*TCC)      // 128
#define OFF_PGEN   (OFF_CSUM + BB)          // 128
#define OFF_CPS    (OFF_PGEN + BB)          // 128
#define OFF_RSUM   (OFF_CPS  + BB)          // 128
#define SCRATCH_FLOATS (OFF_RSUM + BB)

__device__ float g_scratch[SCRATCH_FLOATS];
__device__ __nv_bfloat16 g_hbf[BB * HH];    // h in bf16 (row-major [b][k])

// ---------------- helpers ----------------
__device__ __forceinline__ float sigf(float x) { return 1.0f / (1.0f + expf(-x)); }

__device__ __forceinline__ uint32_t smem_u32(const void* p) {
    uint32_t a;
    asm("{ .reg .u64 t; cvta.to.shared.u64 t, %1; cvt.u32.u64 %0, t; }" : "=r"(a) : "l"(p));
    return a;
}

// ---------------- prep ----------------
__global__ void prep_kernel(const float* __restrict__ W_ih, const float* __restrict__ W_hh,
                            const float* __restrict__ attn_W, const float* __restrict__ cattn_W,
                            const float* __restrict__ b_ih, const float* __restrict__ b_hh,
                            const float* __restrict__ attn_b, const float* __restrict__ cattn_b,
                            float* __restrict__ scratch)
{
    const int WCATN = G4H * KCAT;
    const int WDN   = DCAT * HH;
    const int GN    = BB * G4H;
    const int DN    = BB * DCAT;
    long idx = (long)blockIdx.x * blockDim.x + threadIdx.x;
    if (idx < WCATN) {
        int n = (int)(idx / KCAT), k = (int)(idx % KCAT);
        scratch[OFF_WCAT + idx] = (k < EE) ? W_ih[n*EE + k] : W_hh[n*HH + (k - EE)];
        return;
    }
    idx -= WCATN;
    if (idx < WDN) {
        int n = (int)(idx / HH), k = (int)(idx % HH);
        scratch[OFF_WD + idx] = (n < HH) ? attn_W[n*HH + k] : cattn_W[(n - HH)*HH + k];
        return;
    }
    idx -= WDN;
    if (idx < GN) {
        int n = (int)(idx % G4H);
        scratch[OFF_GATES + idx] = b_ih[n] + b_hh[n];
        return;
    }
    idx -= GN;
    if (idx < DN) {
        int n = (int)(idx % DCAT);
        scratch[OFF_D12 + idx] = (n < HH) ? attn_b[n] : cattn_b[n - HH];
        return;
    }
    idx -= DN;
    if (idx < BB) scratch[OFF_RSUM + idx] = 0.0f;
}

// ---------------- embed ----------------
__global__ void embed_kernel(const int* __restrict__ ids, const float* __restrict__ emb,
                             const float* __restrict__ h0, float* __restrict__ xcat)
{
    int b = blockIdx.x, tid = threadIdx.x;
    int i0 = ids[b*LL + 0], i1 = ids[b*LL + 1], i2 = ids[b*LL + 2], i3 = ids[b*LL + 3];
    if (tid < EE) {
        float s = emb[(long)i0*EE + tid] + emb[(long)i1*EE + tid]
                + emb[(long)i2*EE + tid] + emb[(long)i3*EE + tid];
        xcat[b*KCAT + tid] = tanhf(s * (1.0f / LL));
    }
    for (int j = tid; j < HH; j += blockDim.x)
        xcat[b*KCAT + EE + j] = h0[b*HH + j];
}

// ---------------- small-GEMM (fp32 f32x2) -- gates and d12 -------------------
__global__ __launch_bounds__(256)
void gemm_kernel(const float* __restrict__ X, int ldx,
                 const float* __restrict__ W, int ldw,
                 float* __restrict__ C, int ldc, int N, int K)
{
    __shared__ float Xs[16][130];
    __shared__ float Ws[16][132];

    int n0   = blockIdx.x * 128;
    int klen = K / gridDim.y;
    int kbeg = blockIdx.y * klen;
    int tid  = threadIdx.x;
    int tm   = tid >> 4;
    int tn   = tid & 15;

    unsigned long long acc[4][8];
    #pragma unroll
    for (int p = 0; p < 4; p++)
        #pragma unroll
        for (int j = 0; j < 8; j++) acc[p][j] = 0ull;

    for (int k0 = kbeg; k0 < kbeg + klen; k0 += 16) {
        #pragma unroll
        for (int i = tid; i < 128*16; i += 256) {
            int m = i >> 4, k = i & 15;
            Xs[k][m] = X[(long)m*ldx + k0 + k];
        }
        #pragma unroll
        for (int i = tid; i < 128*16; i += 256) {
            int n = i >> 4, k = i & 15;
            int gn = n0 + n;
            Ws[k][n] = (gn < N) ? W[(long)gn*ldw + k0 + k] : 0.0f;
        }
        __syncthreads();
        #pragma unroll
        for (int k = 0; k < 16; k++) {
            unsigned long long rm[4];
            #pragma unroll
            for (int p = 0; p < 4; p++)
                rm[p] = *(const unsigned long long*)&Xs[k][tm*8 + 2*p];
            float4 w0 = *(const float4*)&Ws[k][tn*8];
            float4 w1 = *(const float4*)&Ws[k][tn*8 + 4];
            float wv[8] = {w0.x, w0.y, w0.z, w0.w, w1.x, w1.y, w1.z, w1.w};
            #pragma unroll
            for (int j = 0; j < 8; j++) {
                unsigned long long bv;
                asm("mov.b64 %0, {%1,%1};" : "=l"(bv) : "f"(wv[j]));
                #pragma unroll
                for (int p = 0; p < 4; p++)
                    asm("fma.rn.f32x2 %0, %1, %2, %0;"
                        : "+l"(acc[p][j]) : "l"(rm[p]), "l"(bv));
            }
        }
        __syncthreads();
    }

    #pragma unroll
    for (int p = 0; p < 4; p++) {
        int m0 = tm*8 + 2*p;
        #pragma unroll
        for (int j = 0; j < 8; j++) {
            int n = n0 + tn*8 + j;
            if (n < N) {
                float2 v = *(float2*)&acc[p][j];
                atomicAdd(&C[(long)m0*ldc + n], v.x);
                atomicAdd(&C[(long)(m0+1)*ldc + n], v.y);
            }
        }
    }
}

// ---------------- LSTM pointwise (+ bf16 h for tensor GEMM) ----------------
__global__ void lstm_kernel(const float* __restrict__ gates, const float* __restrict__ c0,
                            float* __restrict__ h, float* __restrict__ c,
                            __nv_bfloat16* __restrict__ hbf,
                            float* __restrict__ dout, int write_hc)
{
    int b = blockIdx.x, j = threadIdx.x;
    float gi = gates[b*G4H + j];
    float gf = gates[b*G4H + HH + j];
    float gg = gates[b*G4H + 2*HH + j];
    float go = gates[b*G4H + 3*HH + j];
    float cp = c0[b*HH + j];
    float cn = sigf(gf) * cp + sigf(gi) * tanhf(gg);
    float hn = sigf(go) * tanhf(cn);
    h[b*HH + j] = hn;
    c[b*HH + j] = cn;
    hbf[b*HH + j] = __float2bfloat16(hn);
    if (write_hc) {
        dout[(long)BB*NOUT + b*HH + j]           = hn;
        dout[(long)BB*NOUT + BB*HH + b*HH + j]   = cn;
    }
}

// ---------------- one-pass attention (both tensors, blockIdx.z selects) ------
__global__ __launch_bounds__(256)
void attn_kernel(const float* __restrict__ enc0, const float* __restrict__ enc1,
                 const float* __restrict__ dmat,
                 float* __restrict__ pctx, float* __restrict__ psum,
                 float* __restrict__ cexp)
{
    int b = blockIdx.x, ch = blockIdx.y, a = blockIdx.z;
    int tid = threadIdx.x, lane = tid & 31, wid = tid >> 5;
    const float* enc = (a == 0) ? enc0 : enc1;
    int doff = a * HH;
    __shared__ float d_s[HH];
    __shared__ float acc_s[HH];
    __shared__ float sum_s[8];
    for (int i = tid; i < HH; i += 256) {
        d_s[i] = dmat[b*DCAT + doff + i];
        acc_s[i] = 0.0f;
    }
    __syncthreads();

    float acc[16];
    #pragma unroll
    for (int i = 0; i < 16; i++) acc[i] = 0.0f;
    float sume = 0.0f;

    int tbase = ch*128 + wid*16;
    const float* eb = enc + ((long)b*TT + tbase) * HH;
    #pragma unroll 2
    for (int tt = 0; tt < 16; tt++) {
        const float* e = eb + (long)tt*HH;
        float4 ev[4];
        float s = 0.0f;
        #pragma unroll
        for (int i = 0; i < 4; i++) {
            int d0 = lane*4 + 128*i;
            ev[i] = *(const float4*)&e[d0];
            float4 dv = *(const float4*)&d_s[d0];
            s += ev[i].x*dv.x + ev[i].y*dv.y + ev[i].z*dv.z + ev[i].w*dv.w;
        }
        #pragma unroll
        for (int o = 16; o; o >>= 1) s += __shfl_xor_sync(0xFFFFFFFFu, s, o);
        float w = expf(s);
        sume += w;
        if (a == 1 && lane == 0) cexp[b*TCC + tbase + tt] = w;
        #pragma unroll
        for (int i = 0; i < 4; i++) {
            acc[4*i+0] += w * ev[i].x;
            acc[4*i+1] += w * ev[i].y;
            acc[4*i+2] += w * ev[i].z;
            acc[4*i+3] += w * ev[i].w;
        }
    }
    #pragma unroll
    for (int i = 0; i < 16; i++) {
        int d = lane*4 + 128*(i >> 2) + (i & 3);
        atomicAdd(&acc_s[d], acc[i]);
    }
    if (lane == 0) sum_s[wid] = sume;
    __syncthreads();
    for (int i = tid; i < HH; i += 256)
        pctx[(long)a*BB*8*HH + (long)(b*8 + ch)*HH + i] = acc_s[i];
    if (tid == 0) {
        float s = 0.0f;
        #pragma unroll
        for (int w = 0; w < 8; w++) s += sum_s[w];
        psum[a*BB*8 + b*8 + ch] = s;
    }
}

// ---------------- combine attention partials ----------------
__global__ void combine_kernel(const float* __restrict__ pctx, const float* __restrict__ psum,
                               float* __restrict__ ctx, float* __restrict__ csum)
{
    int b = blockIdx.x, a = blockIdx.y, d = threadIdx.x;
    const float* ps = psum + a*BB*8 + b*8;
    float ssum = 0.0f;
    #pragma unroll
    for (int ch = 0; ch < 8; ch++) ssum += ps[ch];
    const float* pc = pctx + (long)a*BB*8*HH + (long)b*8*HH;
    float cv = 0.0f;
    #pragma unroll
    for (int ch = 0; ch < 8; ch++) cv += pc[ch*HH + d];
    ctx[(long)(a*BB + b)*HH + d] = cv / ssum;
    if (a == 1 && d == 0) csum[b] = ssum;
}

// ---------------- p_gen ----------------
__global__ void pgen_kernel(const float* __restrict__ ctx, const float* __restrict__ h,
                            const float* __restrict__ xcat, const float* __restrict__ gen_W,
                            const float* __restrict__ gen_b, const float* __restrict__ sig_b,
                            const int* __restrict__ ci, const float* __restrict__ csum,
                            float* __restrict__ pgen, float* __restrict__ cps)
{
    __shared__ float sred[256];
    __shared__ int   cred[256];
    int b = blockIdx.x, tid = threadIdx.x;
    float part = 0.0f;
    for (int i = tid; i < 3*HH + EE; i += 256) {
        float f;
        if (i < HH)           f = ctx[(long)b*HH + i];
        else if (i < 2*HH)    f = ctx[(long)(BB + b)*HH + (i - HH)];
        else if (i < 3*HH)    f = h[b*HH + (i - 2*HH)];
        else                  f = xcat[b*KCAT + (i - 3*HH)];
        part += f * gen_W[i];
    }
    int cnt = 0;
    for (int t = tid; t < TCC; t += 256) cnt += (ci[b*TCC + t] > 0) ? 1 : 0;
    sred[tid] = part; cred[tid] = cnt;
    __syncthreads();
    for (int o = 128; o; o >>= 1) {
        if (tid < o) { sred[tid] += sred[tid + o]; cred[tid] += cred[tid + o]; }
        __syncthreads();
    }
    if (tid == 0) {
        float z = sred[0] + gen_b[0] + sig_b[0];
        float p = sigf(z);
        if (cred[0] == 0) p = 1.0f;
        pgen[b] = p;
        cps[b]  = (1.0f - p) / csum[b];
    }
}

// ---------------- HMMA bf16 out-projection (base-target mma.sync) -----------
#define OG_KCH 64
#define OG_SA  72
#define OG_SB  72

__global__ __launch_bounds__(128, 4)
void outgemm_kernel(const __nv_bfloat16* __restrict__ hbf,
                    const float* __restrict__ W,
                    const float* __restrict__ bias,
                    float* __restrict__ dout,
                    float* __restrict__ rowsum)
{
    __shared__ __nv_bfloat16 As[128 * OG_SA];
    __shared__ __nv_bfloat16 Bs[64  * OG_SB];
    __shared__ float bias_s[64];
    __shared__ float rs_s[128];

    int tid = threadIdx.x, lane = tid & 31, warp = tid >> 5;
    int n0 = blockIdx.x * 64;

    if (tid < 64) { int n = n0 + tid; bias_s[tid] = (n < VTT) ? bias[n] : 0.0f; }
    rs_s[tid] = 0.0f;

    uint32_t as_b = smem_u32(As);
    uint32_t bs_b = smem_u32(Bs);

    float acc[8][2][4];
    #pragma unroll
    for (int mf = 0; mf < 8; mf++)
        #pragma unroll
        for (int nf = 0; nf < 2; nf++)
            #pragma unroll
            for (int r = 0; r < 4; r++) acc[mf][nf][r] = 0.0f;

    for (int kc = 0; kc < HH; kc += OG_KCH) {
        #pragma unroll
        for (int it = 0; it < 8; it++) {
            int idx = it*128 + tid;
            int m = idx >> 3, kg = idx & 7;
            uint4 v = *(const uint4*)(hbf + (size_t)m*HH + kc + kg*8);
            *(uint4*)(As + m*OG_SA + kg*8) = v;
        }
        #pragma unroll
        for (int it = 0; it < 4; it++) {
            int idx = it*128 + tid;
            int r = idx >> 3, kg = idx & 7;
            int gn = n0 + r;
            float4 v0, v1;
            if (gn < VTT) {
                const float* wp = W + (size_t)gn*HH + kc + kg*8;
                v0 = *(const float4*)wp;
                v1 = *(const float4*)(wp + 4);
            } else {
                v0 = make_float4(0.f,0.f,0.f,0.f);
                v1 = v0;
            }
            __nv_bfloat162 p0 = __floats2bfloat162_rn(v0.x, v0.y);
            __nv_bfloat162 p1 = __floats2bfloat162_rn(v0.z, v0.w);
            __nv_bfloat162 p2 = __floats2bfloat162_rn(v1.x, v1.y);
            __nv_bfloat162 p3 = __floats2bfloat162_rn(v1.z, v1.w);
            uint4 pk;
            pk.x = *reinterpret_cast<uint32_t*>(&p0);
            pk.y = *reinterpret_cast<uint32_t*>(&p1);
            pk.z = *reinterpret_cast<uint32_t*>(&p2);
            pk.w = *reinterpret_cast<uint32_t*>(&p3);
            *(uint4*)(Bs + r*OG_SB + kg*8) = pk;
        }
        __syncthreads();

        #pragma unroll
        for (int ks = 0; ks < 4; ks++) {
            int k0 = ks * 16;
            uint32_t a[8][4];
            #pragma unroll
            for (int mf = 0; mf < 8; mf++) {
                uint32_t addr = as_b + (uint32_t)(((mf*16 + (lane & 15))*OG_SA + k0 + (lane >> 4)*8) * 2);
                asm volatile("ldmatrix.sync.aligned.m8n8.x4.shared.b16 {%0,%1,%2,%3}, [%4];"
                    : "=r"(a[mf][0]), "=r"(a[mf][1]), "=r"(a[mf][2]), "=r"(a[mf][3]) : "r"(addr));
            }
            #pragma unroll
            for (int nf = 0; nf < 2; nf++) {
                uint32_t b0, b1;
                uint32_t baddr = bs_b + (uint32_t)(((warp*16 + nf*8 + (lane & 7))*OG_SB
                                                    + k0 + ((lane >> 3) & 1)*8) * 2);
                asm volatile("ldmatrix.sync.aligned.m8n8.x2.shared.b16 {%0,%1}, [%2];"
                    : "=r"(b0), "=r"(b1) : "r"(baddr));
                #pragma unroll
                for (int mf = 0; mf < 8; mf++) {
                    asm volatile("mma.sync.aligned.m16n8k16.row.col.f32.bf16.bf16.f32 "
                        "{%0,%1,%2,%3}, {%4,%5,%6,%7}, {%8,%9}, {%0,%1,%2,%3};"
                        : "+f"(acc[mf][nf][0]), "+f"(acc[mf][nf][1]),
                          "+f"(acc[mf][nf][2]), "+f"(acc[mf][nf][3])
                        : "r"(a[mf][0]), "r"(a[mf][1]), "r"(a[mf][2]), "r"(a[mf][3]),
                          "r"(b0), "r"(b1));
                }
            }
        }
        __syncthreads();
    }

    float rsp1[8], rsp2[8];
    #pragma unroll
    for (int mf = 0; mf < 8; mf++) { rsp1[mf] = 0.0f; rsp2[mf] = 0.0f; }

    #pragma unroll
    for (int mf = 0; mf < 8; mf++) {
        int r1 = mf*16 + (lane >> 2);
        #pragma unroll
        for (int nf = 0; nf < 2; nf++) {
            int ln = warp*16 + nf*8 + (lane & 3)*2;
            int gn = n0 + ln;
            float bv0 = bias_s[ln], bv1 = bias_s[ln + 1];
            float e0 = expf(acc[mf][nf][0] + bv0);
            float e1 = expf(acc[mf][nf][1] + bv1);
            float e2 = expf(acc[mf][nf][2] + bv0);
            float e3 = expf(acc[mf][nf][3] + bv1);
            float2 w0 = make_float2(e0, e1);
            float2 w1 = make_float2(e2, e3);
            *(float2*)&dout[(long)r1*NOUT + gn]       = w0;
            *(float2*)&dout[(long)(r1 + 8)*NOUT + gn] = w1;
            if (gn < VTT) { rsp1[mf] += e0 + e1; rsp2[mf] += e2 + e3; }
        }
    }
    #pragma unroll
    for (int mf = 0; mf < 8; mf++) {
        float s1 = rsp1[mf], s2 = rsp2[mf];
        s1 += __shfl_xor_sync(0xFFFFFFFFu, s1, 1);
        s1 += __shfl_xor_sync(0xFFFFFFFFu, s1, 2);
        s2 += __shfl_xor_sync(0xFFFFFFFFu, s2, 1);
        s2 += __shfl_xor_sync(0xFFFFFFFFu, s2, 2);
        if ((lane & 3) == 0) {
            atomicAdd(&rs_s[mf*16 + (lane >> 2)], s1);
            atomicAdd(&rs_s[mf*16 + (lane >> 2) + 8], s2);
        }
    }
    __syncthreads();
    atomicAdd(&rowsum[tid], rs_s[tid]);
}

// ---------------- scatter copy-mass into EXP domain --------------------------
// dout holds exp(logit). out = (pgen/rowsum) * (exp + copy*rowsum/pgen), so add
// cexp[b][t] * cps[b] * rowsum[b] / pgen[b] here; final kernel applies scale+log.
__global__ void scatter_kernel(float* __restrict__ dout, const int* __restrict__ ci,
                               const float* __restrict__ cexp, const float* __restrict__ cps,
                               const float* __restrict__ rowsum, const float* __restrict__ pgen)
{
    int b = blockIdx.x;
    float f = cps[b] * rowsum[b] / pgen[b];
    int t = blockIdx.y * 256 + threadIdx.x;
    int idx = ci[b*TCC + t];
    atomicAdd(&dout[(long)b*NOUT + idx], f * cexp[b*TCC + t]);
}

// ---------------- final: out = log(clip(val * pgen/rowsum)); OOV = log(1e-10) -
__global__ void final_kernel(float* __restrict__ dout, const float* __restrict__ pgen,
                             const float* __restrict__ rowsum)
{
    const float LOGCLIP = -23.025850929940457f;  // log(1e-10)
    long i2 = (long)blockIdx.x * blockDim.x + threadIdx.x;   // float2 index
    if (i2 >= (long)BB*NOUT/2) return;
    long idx = i2 * 2;
    int b = (int)(idx / NOUT);
    int v = (int)(idx % NOUT);
    float2 val = *(float2*)&dout[idx];
    float2 out;
    if (v < VTT) {
        float sc = pgen[b] / rowsum[b];
        out.x = logf(fmaxf(val.x * sc, 1e-10f));
        out.y = logf(fmaxf(val.y * sc, 1e-10f));
    } else {
        out.x = LOGCLIP;
        out.y = LOGCLIP;
    }
    *(float2*)&dout[idx] = out;
}

// ---------------- launcher ----------------
extern "C" void kernel_launch(void* const* d_in, const int* in_sizes, int n_in,
                              void* d_out, int out_size)
{
    const int*   ids     = (const int*)  d_in[0];
    const float* h0      = (const float*)d_in[1];
    const float* c0      = (const float*)d_in[2];
    const float* enc     = (const float*)d_in[3];
    const float* cenc    = (const float*)d_in[4];
    const int*   ci      = (const int*)  d_in[5];
    const float* emb     = (const float*)d_in[6];
    const float* W_ih    = (const float*)d_in[7];
    const float* W_hh    = (const float*)d_in[8];
    const float* b_ih    = (const float*)d_in[9];
    const float* b_hh    = (const float*)d_in[10];
    const float* attn_W  = (const float*)d_in[11];
    const float* attn_b  = (const float*)d_in[12];
    const float* cattn_W = (const float*)d_in[13];
    const float* cattn_b = (const float*)d_in[14];
    const float* gen_W   = (const float*)d_in[15];
    const float* gen_b   = (const float*)d_in[16];
    const float* sig_b   = (const float*)d_in[17];
    const float* out_W   = (const float*)d_in[18];
    const float* out_b   = (const float*)d_in[19];
    float* dout = (float*)d_out;

    float* S = nullptr;
    cudaGetSymbolAddress((void**)&S, g_scratch);
    __nv_bfloat16* hbf = nullptr;
    cudaGetSymbolAddress((void**)&hbf, g_hbf);

    float* xcat  = S + OFF_XCAT;
    float* wcat  = S + OFF_WCAT;
    float* wd    = S + OFF_WD;
    float* gates = S + OFF_GATES;
    float* hbuf  = S + OFF_H;
    float* cbuf  = S + OFF_C;
    float* d12   = S + OFF_D12;
    float* pctx  = S + OFF_PCTX;
    float* psum  = S + OFF_PSUM;
    float* ctx   = S + OFF_CTX;
    float* cexp  = S + OFF_CEXP;
    float* csum  = S + OFF_CSUM;
    float* pgen  = S + OFF_PGEN;
    float* cps   = S + OFF_CPS;
    float* rsum  = S + OFF_RSUM;

    const long prep_n = (long)G4H*KCAT + (long)DCAT*HH + (long)BB*G4H + (long)BB*DCAT + BB;
    prep_kernel<<<(int)((prep_n + 255) / 256), 256>>>(W_ih, W_hh, attn_W, cattn_W,
                                                      b_ih, b_hh, attn_b, cattn_b, S);

    embed_kernel<<<BB, 256>>>(ids, emb, h0, xcat);

    // gates = Xcat @ Wcat^T (+bias preinit), split-K=8
    gemm_kernel<<<dim3(G4H/128, 8), 256>>>(xcat, KCAT, wcat, KCAT, gates, G4H, G4H, KCAT);

    int write_hc = (out_size >= BB*NOUT + 2*BB*HH) ? 1 : 0;
    lstm_kernel<<<BB, HH>>>(gates, c0, hbuf, cbuf, hbf, dout, write_hc);

    // d12 = dec @ [attn_W;cattn_W]^T (+bias preinit), split-K=8
    gemm_kernel<<<dim3(DCAT/128, 8), 256>>>(hbuf, HH, wd, HH, d12, DCAT, DCAT, HH);

    // out logits -> exp + rowsum via HMMA bf16 (independent of attention)
    outgemm_kernel<<<OGTILES, 128>>>(hbf, out_W, out_b, dout, rsum);

    // both attentions in one launch (z=0: source, z=1: context + cexp)
    attn_kernel<<<dim3(BB, 8, 2), 256>>>(enc, cenc, d12, pctx, psum, cexp);

    combine_kernel<<<dim3(BB, 2), HH>>>(pctx, psum, ctx, csum);

    pgen_kernel<<<BB, 256>>>(ctx, hbuf, xcat, gen_W, gen_b, sig_b, ci, csum, pgen, cps);

    scatter_kernel<<<dim3(BB, TCC/256), 256>>>(dout, ci, cexp, cps, rsum, pgen);

    long n2 = (long)BB * NOUT / 2;
    final_kernel<<<(int)((n2 + 255) / 256), 256>>>(dout, pgen, rsum);
}

// round 11
// speedup vs baseline: 1.9887x; 1.0897x over previous
#include <cuda_runtime.h>
#include <cuda_bf16.h>
#include <math.h>
#include <stdint.h>

// ---------------- problem constants ----------------
#define BB   128
#define TT   1024
#define TCC  1024
#define LL   4
#define EE   256
#define HH   512
#define VTT  50000
#define OOVN 50
#define NOUT (VTT + OOVN)   // 50050
#define G4H  2048           // 4*H
#define KCAT 768            // E + H
#define DCAT 1024           // 2*H (d1,d2)
#define OG_CNT ((VTT + 63) / 64)      // 782 outgemm tiles
#define AT_CNT (BB * 8 * 2)           // 2048 attention blocks
#define MG_CNT (OG_CNT + AT_CNT)      // 2830 merged grid

// ---------------- scratch ----------------
#define OFF_XCAT   0                        // 128*768
#define OFF_WCAT   (OFF_XCAT + BB*KCAT)     // 2048*768
#define OFF_WD     (OFF_WCAT + G4H*KCAT)    // 1024*512
#define OFF_GATES  (OFF_WD   + DCAT*HH)     // 128*2048
#define OFF_H      (OFF_GATES+ BB*G4H)      // 128*512
#define OFF_C      (OFF_H    + BB*HH)       // 128*512
#define OFF_D12    (OFF_C    + BB*HH)       // 128*1024
#define OFF_PCTX   (OFF_D12  + BB*DCAT)     // 2*128*8*512
#define OFF_PSUM   (OFF_PCTX + 2*BB*8*HH)   // 2*128*8
#define OFF_CEXP   (OFF_PSUM + 2*BB*8)      // 128*1024
#define OFF_PGEN   (OFF_CEXP + BB*TCC)      // 128
#define OFF_SF     (OFF_PGEN + BB)          // 128 (scatter factor)
#define OFF_RSUM   (OFF_SF   + BB)          // 128
#define SCRATCH_FLOATS (OFF_RSUM + BB)

__device__ float g_scratch[SCRATCH_FLOATS];
__device__ __nv_bfloat16 g_hbf[BB * HH];    // h in bf16 (row-major [b][k])

// ---------------- helpers ----------------
__device__ __forceinline__ float sigf(float x) { return 1.0f / (1.0f + expf(-x)); }

__device__ __forceinline__ uint32_t smem_u32(const void* p) {
    uint32_t a;
    asm("{ .reg .u64 t; cvta.to.shared.u64 t, %1; cvt.u32.u64 %0, t; }" : "=r"(a) : "l"(p));
    return a;
}

// ---------------- prep ----------------
__global__ void prep_kernel(const float* __restrict__ W_ih, const float* __restrict__ W_hh,
                            const float* __restrict__ attn_W, const float* __restrict__ cattn_W,
                            const float* __restrict__ b_ih, const float* __restrict__ b_hh,
                            const float* __restrict__ attn_b, const float* __restrict__ cattn_b,
                            float* __restrict__ scratch)
{
    const int WCATN = G4H * KCAT;
    const int WDN   = DCAT * HH;
    const int GN    = BB * G4H;
    const int DN    = BB * DCAT;
    long idx = (long)blockIdx.x * blockDim.x + threadIdx.x;
    if (idx < WCATN) {
        int n = (int)(idx / KCAT), k = (int)(idx % KCAT);
        scratch[OFF_WCAT + idx] = (k < EE) ? W_ih[n*EE + k] : W_hh[n*HH + (k - EE)];
        return;
    }
    idx -= WCATN;
    if (idx < WDN) {
        int n = (int)(idx / HH), k = (int)(idx % HH);
        scratch[OFF_WD + idx] = (n < HH) ? attn_W[n*HH + k] : cattn_W[(n - HH)*HH + k];
        return;
    }
    idx -= WDN;
    if (idx < GN) {
        int n = (int)(idx % G4H);
        scratch[OFF_GATES + idx] = b_ih[n] + b_hh[n];
        return;
    }
    idx -= GN;
    if (idx < DN) {
        int n = (int)(idx % DCAT);
        scratch[OFF_D12 + idx] = (n < HH) ? attn_b[n] : cattn_b[n - HH];
        return;
    }
    idx -= DN;
    if (idx < BB) scratch[OFF_RSUM + idx] = 0.0f;
}

// ---------------- embed ----------------
__global__ void embed_kernel(const int* __restrict__ ids, const float* __restrict__ emb,
                             const float* __restrict__ h0, float* __restrict__ xcat)
{
    int b = blockIdx.x, tid = threadIdx.x;
    int i0 = ids[b*LL + 0], i1 = ids[b*LL + 1], i2 = ids[b*LL + 2], i3 = ids[b*LL + 3];
    if (tid < EE) {
        float s = emb[(long)i0*EE + tid] + emb[(long)i1*EE + tid]
                + emb[(long)i2*EE + tid] + emb[(long)i3*EE + tid];
        xcat[b*KCAT + tid] = tanhf(s * (1.0f / LL));
    }
    for (int j = tid; j < HH; j += blockDim.x)
        xcat[b*KCAT + EE + j] = h0[b*HH + j];
}

// ---------------- small-GEMM (fp32 f32x2) -- gates and d12 -------------------
__global__ __launch_bounds__(256)
void gemm_kernel(const float* __restrict__ X, int ldx,
                 const float* __restrict__ W, int ldw,
                 float* __restrict__ C, int ldc, int N, int K)
{
    __shared__ float Xs[16][130];
    __shared__ float Ws[16][132];

    int n0   = blockIdx.x * 128;
    int klen = K / gridDim.y;
    int kbeg = blockIdx.y * klen;
    int tid  = threadIdx.x;
    int tm   = tid >> 4;
    int tn   = tid & 15;

    unsigned long long acc[4][8];
    #pragma unroll
    for (int p = 0; p < 4; p++)
        #pragma unroll
        for (int j = 0; j < 8; j++) acc[p][j] = 0ull;

    for (int k0 = kbeg; k0 < kbeg + klen; k0 += 16) {
        #pragma unroll
        for (int i = tid; i < 128*16; i += 256) {
            int m = i >> 4, k = i & 15;
            Xs[k][m] = X[(long)m*ldx + k0 + k];
        }
        #pragma unroll
        for (int i = tid; i < 128*16; i += 256) {
            int n = i >> 4, k = i & 15;
            int gn = n0 + n;
            Ws[k][n] = (gn < N) ? W[(long)gn*ldw + k0 + k] : 0.0f;
        }
        __syncthreads();
        #pragma unroll
        for (int k = 0; k < 16; k++) {
            unsigned long long rm[4];
            #pragma unroll
            for (int p = 0; p < 4; p++)
                rm[p] = *(const unsigned long long*)&Xs[k][tm*8 + 2*p];
            float4 w0 = *(const float4*)&Ws[k][tn*8];
            float4 w1 = *(const float4*)&Ws[k][tn*8 + 4];
            float wv[8] = {w0.x, w0.y, w0.z, w0.w, w1.x, w1.y, w1.z, w1.w};
            #pragma unroll
            for (int j = 0; j < 8; j++) {
                unsigned long long bv;
                asm("mov.b64 %0, {%1,%1};" : "=l"(bv) : "f"(wv[j]));
                #pragma unroll
                for (int p = 0; p < 4; p++)
                    asm("fma.rn.f32x2 %0, %1, %2, %0;"
                        : "+l"(acc[p][j]) : "l"(rm[p]), "l"(bv));
            }
        }
        __syncthreads();
    }

    #pragma unroll
    for (int p = 0; p < 4; p++) {
        int m0 = tm*8 + 2*p;
        #pragma unroll
        for (int j = 0; j < 8; j++) {
            int n = n0 + tn*8 + j;
            if (n < N) {
                float2 v = *(float2*)&acc[p][j];
                atomicAdd(&C[(long)m0*ldc + n], v.x);
                atomicAdd(&C[(long)(m0+1)*ldc + n], v.y);
            }
        }
    }
}

// ---------------- LSTM pointwise (+ bf16 h for tensor GEMM) ----------------
__global__ void lstm_kernel(const float* __restrict__ gates, const float* __restrict__ c0,
                            float* __restrict__ h, float* __restrict__ c,
                            __nv_bfloat16* __restrict__ hbf,
                            float* __restrict__ dout, int write_hc)
{
    int b = blockIdx.x, j = threadIdx.x;
    float gi = gates[b*G4H + j];
    float gf = gates[b*G4H + HH + j];
    float gg = gates[b*G4H + 2*HH + j];
    float go = gates[b*G4H + 3*HH + j];
    float cp = c0[b*HH + j];
    float cn = sigf(gf) * cp + sigf(gi) * tanhf(gg);
    float hn = sigf(go) * tanhf(cn);
    h[b*HH + j] = hn;
    c[b*HH + j] = cn;
    hbf[b*HH + j] = __float2bfloat16(hn);
    if (write_hc) {
        dout[(long)BB*NOUT + b*HH + j]           = hn;
        dout[(long)BB*NOUT + BB*HH + b*HH + j]   = cn;
    }
}

// ---------------- MERGED: attention (2048 blocks) + HMMA outgemm (782) -------
// Bresenham interleave: block is outgemm iff floor((bid+1)*782/2830) increments.
#define OG_KCH 64
#define OG_SA  72
#define OG_SB  72
// og smem: As 128*72*2 + Bs 64*72*2 + bias 64*4 + rs 128*4 = 28416 B
#define MG_SMEM 28416

__global__ __launch_bounds__(256)
void merged_kernel(const float* __restrict__ enc0, const float* __restrict__ enc1,
                   const float* __restrict__ dmat,
                   float* __restrict__ pctx, float* __restrict__ psum,
                   float* __restrict__ cexp,
                   const __nv_bfloat16* __restrict__ hbf,
                   const float* __restrict__ W,
                   const float* __restrict__ bias,
                   float* __restrict__ dout,
                   float* __restrict__ rowsum)
{
    __shared__ __align__(16) char smem_raw[MG_SMEM];
    int bid = blockIdx.x;
    int tid = threadIdx.x, lane = tid & 31, warp = tid >> 5;

    long t64 = (long)bid * OG_CNT;
    int og_lo = (int)(t64 / MG_CNT);
    int og_hi = (int)((t64 + OG_CNT) / MG_CNT);
    bool is_og = (og_hi > og_lo);

    if (is_og) {
        // ---------------- outgemm path: tile n0..n0+63, 8 warps x n8 slab ----
        int n0 = og_lo * 64;
        __nv_bfloat16* As = (__nv_bfloat16*)smem_raw;
        __nv_bfloat16* Bs = As + 128 * OG_SA;
        float* bias_s = (float*)(Bs + 64 * OG_SB);
        float* rs_s   = bias_s + 64;

        if (tid < 64) { int n = n0 + tid; bias_s[tid] = (n < VTT) ? bias[n] : 0.0f; }
        if (tid < 128) rs_s[tid] = 0.0f;

        uint32_t as_b = smem_u32(As);
        uint32_t bs_b = smem_u32(Bs);

        float acc[8][4];
        #pragma unroll
        for (int mf = 0; mf < 8; mf++)
            #pragma unroll
            for (int r = 0; r < 4; r++) acc[mf][r] = 0.0f;

        for (int kc = 0; kc < HH; kc += OG_KCH) {
            // A chunk 128x64 bf16: 1024 uint4, 4/thread
            #pragma unroll
            for (int it = 0; it < 4; it++) {
                int idx = it*256 + tid;
                int m = idx >> 3, kg = idx & 7;
                uint4 v = *(const uint4*)(hbf + (size_t)m*HH + kc + kg*8);
                *(uint4*)(As + m*OG_SA + kg*8) = v;
            }
            // B chunk 64x64 fp32->bf16: 512 uint4, 2/thread
            #pragma unroll
            for (int it = 0; it < 2; it++) {
                int idx = it*256 + tid;
                int r = idx >> 3, kg = idx & 7;
                int gn = n0 + r;
                float4 v0, v1;
                if (gn < VTT) {
                    const float* wp = W + (size_t)gn*HH + kc + kg*8;
                    v0 = *(const float4*)wp;
                    v1 = *(const float4*)(wp + 4);
                } else {
                    v0 = make_float4(0.f,0.f,0.f,0.f);
                    v1 = v0;
                }
                __nv_bfloat162 p0 = __floats2bfloat162_rn(v0.x, v0.y);
                __nv_bfloat162 p1 = __floats2bfloat162_rn(v0.z, v0.w);
                __nv_bfloat162 p2 = __floats2bfloat162_rn(v1.x, v1.y);
                __nv_bfloat162 p3 = __floats2bfloat162_rn(v1.z, v1.w);
                uint4 pk;
                pk.x = *reinterpret_cast<uint32_t*>(&p0);
                pk.y = *reinterpret_cast<uint32_t*>(&p1);
                pk.z = *reinterpret_cast<uint32_t*>(&p2);
                pk.w = *reinterpret_cast<uint32_t*>(&p3);
                *(uint4*)(Bs + r*OG_SB + kg*8) = pk;
            }
            __syncthreads();

            #pragma unroll
            for (int ks = 0; ks < 4; ks++) {
                int k0 = ks * 16;
                uint32_t b0, b1;
                uint32_t baddr = bs_b + (uint32_t)(((warp*8 + (lane & 7))*OG_SB
                                                    + k0 + ((lane >> 3) & 1)*8) * 2);
                asm volatile("ldmatrix.sync.aligned.m8n8.x2.shared.b16 {%0,%1}, [%2];"
                    : "=r"(b0), "=r"(b1) : "r"(baddr));
                #pragma unroll
                for (int mf = 0; mf < 8; mf++) {
                    uint32_t a0, a1, a2, a3;
                    uint32_t aaddr = as_b + (uint32_t)(((mf*16 + (lane & 15))*OG_SA
                                                        + k0 + (lane >> 4)*8) * 2);
                    asm volatile("ldmatrix.sync.aligned.m8n8.x4.shared.b16 {%0,%1,%2,%3}, [%4];"
                        : "=r"(a0), "=r"(a1), "=r"(a2), "=r"(a3) : "r"(aaddr));
                    asm volatile("mma.sync.aligned.m16n8k16.row.col.f32.bf16.bf16.f32 "
                        "{%0,%1,%2,%3}, {%4,%5,%6,%7}, {%8,%9}, {%0,%1,%2,%3};"
                        : "+f"(acc[mf][0]), "+f"(acc[mf][1]), "+f"(acc[mf][2]), "+f"(acc[mf][3])
                        : "r"(a0), "r"(a1), "r"(a2), "r"(a3), "r"(b0), "r"(b1));
                }
            }
            __syncthreads();
        }

        // epilogue: exp(+bias), float2 stores, rowsum
        int ln = warp*8 + (lane & 3)*2;
        int gn = n0 + ln;
        float bv0 = bias_s[ln], bv1 = bias_s[ln + 1];
        float rsp1[8], rsp2[8];
        #pragma unroll
        for (int mf = 0; mf < 8; mf++) {
            int r1 = mf*16 + (lane >> 2);
            float e0 = expf(acc[mf][0] + bv0);
            float e1 = expf(acc[mf][1] + bv1);
            float e2 = expf(acc[mf][2] + bv0);
            float e3 = expf(acc[mf][3] + bv1);
            *(float2*)&dout[(long)r1*NOUT + gn]       = make_float2(e0, e1);
            *(float2*)&dout[(long)(r1 + 8)*NOUT + gn] = make_float2(e2, e3);
            bool v = (gn < VTT);
            rsp1[mf] = v ? (e0 + e1) : 0.0f;
            rsp2[mf] = v ? (e2 + e3) : 0.0f;
        }
        #pragma unroll
        for (int mf = 0; mf < 8; mf++) {
            float s1 = rsp1[mf], s2 = rsp2[mf];
            s1 += __shfl_xor_sync(0xFFFFFFFFu, s1, 1);
            s1 += __shfl_xor_sync(0xFFFFFFFFu, s1, 2);
            s2 += __shfl_xor_sync(0xFFFFFFFFu, s2, 1);
            s2 += __shfl_xor_sync(0xFFFFFFFFu, s2, 2);
            if ((lane & 3) == 0) {
                atomicAdd(&rs_s[mf*16 + (lane >> 2)], s1);
                atomicAdd(&rs_s[mf*16 + (lane >> 2) + 8], s2);
            }
        }
        __syncthreads();
        if (tid < 128) atomicAdd(&rowsum[tid], rs_s[tid]);
    } else {
        // ---------------- attention path ------------------------------------
        int aid = bid - og_lo;                  // 0..2047
        int a  = aid & 1;
        int ch = (aid >> 1) & 7;
        int b  = aid >> 4;
        const float* enc = (a == 0) ? enc0 : enc1;
        int doff = a * HH;

        float* d_s   = (float*)smem_raw;
        float* acc_s = d_s + HH;
        float* sum_s = acc_s + HH;

        for (int i = tid; i < HH; i += 256) {
            d_s[i] = dmat[b*DCAT + doff + i];
            acc_s[i] = 0.0f;
        }
        __syncthreads();

        float acc[16];
        #pragma unroll
        for (int i = 0; i < 16; i++) acc[i] = 0.0f;
        float sume = 0.0f;

        int tbase = ch*128 + warp*16;
        const float* eb = enc + ((long)b*TT + tbase) * HH;
        #pragma unroll 2
        for (int tt = 0; tt < 16; tt++) {
            const float* e = eb + (long)tt*HH;
            float4 ev[4];
            float s = 0.0f;
            #pragma unroll
            for (int i = 0; i < 4; i++) {
                int d0 = lane*4 + 128*i;
                ev[i] = *(const float4*)&e[d0];
                float4 dv = *(const float4*)&d_s[d0];
                s += ev[i].x*dv.x + ev[i].y*dv.y + ev[i].z*dv.z + ev[i].w*dv.w;
            }
            #pragma unroll
            for (int o = 16; o; o >>= 1) s += __shfl_xor_sync(0xFFFFFFFFu, s, o);
            float w = expf(s);
            sume += w;
            if (a == 1 && lane == 0) cexp[b*TCC + tbase + tt] = w;
            #pragma unroll
            for (int i = 0; i < 4; i++) {
                acc[4*i+0] += w * ev[i].x;
                acc[4*i+1] += w * ev[i].y;
                acc[4*i+2] += w * ev[i].z;
                acc[4*i+3] += w * ev[i].w;
            }
        }
        #pragma unroll
        for (int i = 0; i < 16; i++) {
            int d = lane*4 + 128*(i >> 2) + (i & 3);
            atomicAdd(&acc_s[d], acc[i]);
        }
        if (lane == 0) sum_s[warp] = sume;
        __syncthreads();
        for (int i = tid; i < HH; i += 256)
            pctx[(long)a*BB*8*HH + (long)(b*8 + ch)*HH + i] = acc_s[i];
        if (tid == 0) {
            float s = 0.0f;
            #pragma unroll
            for (int w = 0; w < 8; w++) s += sum_s[w];
            psum[a*BB*8 + b*8 + ch] = s;
        }
    }
}

// ---------------- fused combine + p_gen + scatter factor ---------------------
__global__ void pgen_fused_kernel(const float* __restrict__ pctx, const float* __restrict__ psum,
                                  const float* __restrict__ h, const float* __restrict__ xcat,
                                  const float* __restrict__ gen_W, const float* __restrict__ gen_b,
                                  const float* __restrict__ sig_b, const int* __restrict__ ci,
                                  const float* __restrict__ rowsum,
                                  float* __restrict__ pgen, float* __restrict__ sf)
{
    __shared__ float sred[256];
    __shared__ int   cred[256];
    int b = blockIdx.x, tid = threadIdx.x;

    float ssum0 = 0.0f, ssum1 = 0.0f;
    #pragma unroll
    for (int chn = 0; chn < 8; chn++) {
        ssum0 += psum[b*8 + chn];
        ssum1 += psum[BB*8 + b*8 + chn];
    }
    float inv0 = 1.0f / ssum0, inv1 = 1.0f / ssum1;

    float part = 0.0f;
    for (int i = tid; i < HH; i += 256) {
        float c0 = 0.0f, c1 = 0.0f;
        #pragma unroll
        for (int chn = 0; chn < 8; chn++) {
            c0 += pctx[(long)(b*8 + chn)*HH + i];
            c1 += pctx[(long)BB*8*HH + (long)(b*8 + chn)*HH + i];
        }
        part += c0 * inv0 * gen_W[i] + c1 * inv1 * gen_W[HH + i]
              + h[b*HH + i] * gen_W[2*HH + i];
    }
    for (int i = tid; i < EE; i += 256)
        part += xcat[b*KCAT + i] * gen_W[3*HH + i];

    int cnt = 0;
    for (int t = tid; t < TCC; t += 256) cnt += (ci[b*TCC + t] > 0) ? 1 : 0;
    sred[tid] = part; cred[tid] = cnt;
    __syncthreads();
    for (int o = 128; o; o >>= 1) {
        if (tid < o) { sred[tid] += sred[tid + o]; cred[tid] += cred[tid + o]; }
        __syncthreads();
    }
    if (tid == 0) {
        float z = sred[0] + gen_b[0] + sig_b[0];
        float p = sigf(z);
        if (cred[0] == 0) p = 1.0f;
        pgen[b] = p;
        // scatter adds in exp-domain: factor = (1-p)/csum * rowsum / p
        sf[b] = (1.0f - p) * inv1 * rowsum[b] / p;
    }
}

// ---------------- scatter copy-mass into EXP domain --------------------------
__global__ void scatter_kernel(float* __restrict__ dout, const int* __restrict__ ci,
                               const float* __restrict__ cexp, const float* __restrict__ sf)
{
    int b = blockIdx.x;
    float f = sf[b];
    int t = blockIdx.y * 256 + threadIdx.x;
    int idx = ci[b*TCC + t];
    atomicAdd(&dout[(long)b*NOUT + idx], f * cexp[b*TCC + t]);
}

// ---------------- final: out = log(clip(val * pgen/rowsum)); OOV = log(1e-10) -
__global__ void final_kernel(float* __restrict__ dout, const float* __restrict__ pgen,
                             const float* __restrict__ rowsum)
{
    const float LOGCLIP = -23.025850929940457f;  // log(1e-10)
    long i2 = (long)blockIdx.x * blockDim.x + threadIdx.x;   // float2 index
    if (i2 >= (long)BB*NOUT/2) return;
    long idx = i2 * 2;
    int b = (int)(idx / NOUT);
    int v = (int)(idx % NOUT);
    float2 val = *(float2*)&dout[idx];
    float2 out;
    if (v < VTT) {
        float sc = pgen[b] / rowsum[b];
        out.x = logf(fmaxf(val.x * sc, 1e-10f));
        out.y = logf(fmaxf(val.y * sc, 1e-10f));
    } else {
        out.x = LOGCLIP;
        out.y = LOGCLIP;
    }
    *(float2*)&dout[idx] = out;
}

// ---------------- launcher ----------------
extern "C" void kernel_launch(void* const* d_in, const int* in_sizes, int n_in,
                              void* d_out, int out_size)
{
    const int*   ids     = (const int*)  d_in[0];
    const float* h0      = (const float*)d_in[1];
    const float* c0      = (const float*)d_in[2];
    const float* enc     = (const float*)d_in[3];
    const float* cenc    = (const float*)d_in[4];
    const int*   ci      = (const int*)  d_in[5];
    const float* emb     = (const float*)d_in[6];
    const float* W_ih    = (const float*)d_in[7];
    const float* W_hh    = (const float*)d_in[8];
    const float* b_ih    = (const float*)d_in[9];
    const float* b_hh    = (const float*)d_in[10];
    const float* attn_W  = (const float*)d_in[11];
    const float* attn_b  = (const float*)d_in[12];
    const float* cattn_W = (const float*)d_in[13];
    const float* cattn_b = (const float*)d_in[14];
    const float* gen_W   = (const float*)d_in[15];
    const float* gen_b   = (const float*)d_in[16];
    const float* sig_b   = (const float*)d_in[17];
    const float* out_W   = (const float*)d_in[18];
    const float* out_b   = (const float*)d_in[19];
    float* dout = (float*)d_out;

    float* S = nullptr;
    cudaGetSymbolAddress((void**)&S, g_scratch);
    __nv_bfloat16* hbf = nullptr;
    cudaGetSymbolAddress((void**)&hbf, g_hbf);

    float* xcat  = S + OFF_XCAT;
    float* wcat  = S + OFF_WCAT;
    float* wd    = S + OFF_WD;
    float* gates = S + OFF_GATES;
    float* hbuf  = S + OFF_H;
    float* cbuf  = S + OFF_C;
    float* d12   = S + OFF_D12;
    float* pctx  = S + OFF_PCTX;
    float* psum  = S + OFF_PSUM;
    float* cexp  = S + OFF_CEXP;
    float* pgen  = S + OFF_PGEN;
    float* sf    = S + OFF_SF;
    float* rsum  = S + OFF_RSUM;

    const long prep_n = (long)G4H*KCAT + (long)DCAT*HH + (long)BB*G4H + (long)BB*DCAT + BB;
    prep_kernel<<<(int)((prep_n + 255) / 256), 256>>>(W_ih, W_hh, attn_W, cattn_W,
                                                      b_ih, b_hh, attn_b, cattn_b, S);

    embed_kernel<<<BB, 256>>>(ids, emb, h0, xcat);

    // gates = Xcat @ Wcat^T (+bias preinit), split-K=8
    gemm_kernel<<<dim3(G4H/128, 8), 256>>>(xcat, KCAT, wcat, KCAT, gates, G4H, G4H, KCAT);

    int write_hc = (out_size >= BB*NOUT + 2*BB*HH) ? 1 : 0;
    lstm_kernel<<<BB, HH>>>(gates, c0, hbuf, cbuf, hbf, dout, write_hc);

    // d12 = dec @ [attn_W;cattn_W]^T (+bias preinit), split-K=8
    gemm_kernel<<<dim3(DCAT/128, 8), 256>>>(hbuf, HH, wd, HH, d12, DCAT, DCAT, HH);

    // merged: both attentions + HMMA out-projection, interleaved for overlap
    merged_kernel<<<MG_CNT, 256>>>(enc, cenc, d12, pctx, psum, cexp,
                                   hbf, out_W, out_b, dout, rsum);

    // fused combine + p_gen + scatter factor
    pgen_fused_kernel<<<BB, 256>>>(pctx, psum, hbuf, xcat, gen_W, gen_b, sig_b,
                                   ci, rsum, pgen, sf);

    scatter_kernel<<<dim3(BB, TCC/256), 256>>>(dout, ci, cexp, sf);

    long n2 = (long)BB * NOUT / 2;
    final_kernel<<<(int)((n2 + 255) / 256), 256>>>(dout, pgen, rsum);
}